// round 17
// baseline (speedup 1.0000x reference)
#include <cuda_runtime.h>
#include <math.h>

#define L2L   2
#define HID   512
#define TMAX  20
#define VOC   10000
#define BATCH 32
#define SPOS  49
#define VP    10240   // 1280 col-tiles * 8
#define NB    148
#define NT    256
#define GW    (NB*8)  // 1184 global warps
typedef unsigned long long ull;

// ---------------- weights transposed: WT[k][n] = W[n][k] ----------------
__device__ float g_WihT[L2L][HID][4*HID];
__device__ float g_WhhT[L2L][HID][4*HID];
__device__ float g_WqT[HID][HID];
__device__ float g_hattWT[2*HID][HID];
__device__ float g_projWT[HID][VP];
// ---------------- plain row-major activations ----------------
__device__ float g_keys[BATCH][SPOS][HID];
__device__ float g_vals[BATCH][SPOS][HID];
__device__ float g_h0[BATCH][HID];
__device__ float g_h1[BATCH][HID];
__device__ float g_hcat[2*BATCH][HID];     // [l*32+b][j]
__device__ float g_attn[2*BATCH][HID];
__device__ float g_emb[BATCH][HID];
__device__ float g_c[L2L*BATCH*HID];
// ---------------- split-K partial buffers ----------------
__device__ float g_Pg[32][BATCH][4*HID];   // lstm: 16 ih + 16 hh slices
__device__ float g_Pp[16][BATCH][VP];      // proj: 16 slices
__device__ float g_Pq[16][2*BATCH][HID];   // q: 16 slices
__device__ float g_Ph[64][2*BATCH][HID];   // hatt: 64 slices
__device__ float g_tmp[TMAX][BATCH][VOC];
__device__ float g_amv[BATCH][40];
__device__ int   g_ami[BATCH][40];
__device__ unsigned g_bar;

__device__ __forceinline__ void fma2(ull &a, ull x, ull w){
    asm("fma.rn.f32x2 %0, %1, %2, %0;" : "+l"(a) : "l"(x), "l"(w));
}
__device__ __forceinline__ ull pack2(float w){
    ull r;
    asm("mov.b64 %0, {%1, %1};" : "=l"(r) : "f"(w));
    return r;
}

// ---------------- grid-wide barrier ----------------
__device__ __forceinline__ void gridbar(){
    __syncthreads();
    if (threadIdx.x == 0){
        __threadfence();
        unsigned ret = atomicAdd(&g_bar, 1u);
        unsigned gen = ret >> 16;
        if ((ret & 0xFFFFu) == NB - 1u){
            atomicAdd(&g_bar, 0x10000u - NB);
        } else {
            while (((*(volatile unsigned*)&g_bar) >> 16) == gen){ }
        }
        __threadfence();
    }
    __syncthreads();
}

// ---------------- GEMM thread-unit: 8 cols x 16 rows, KC k's ----------------
// P[(r0+r)*ldo + n0 + c] = sum_{k in [koff,koff+KC)} X[(r0+r)*HID + k] * WT[k*ldw + n0 + c]
__device__ __forceinline__ void gunit16(const float* __restrict__ X, int r0,
        const float* __restrict__ WT, int ldw, int koff, int KC,
        float* __restrict__ P, int ldo, int n0){
    ull acc[16][4];
    #pragma unroll
    for (int r = 0; r < 16; r++)
        #pragma unroll
        for (int c = 0; c < 4; c++) acc[r][c] = 0ULL;
    #pragma unroll 2
    for (int k4 = 0; k4 < KC; k4 += 4){
        const float* wb = WT + (size_t)(koff + k4) * ldw + n0;
        ulonglong2 w[4][2];
        #pragma unroll
        for (int kk = 0; kk < 4; kk++){
            w[kk][0] = *reinterpret_cast<const ulonglong2*>(wb + (size_t)kk * ldw);
            w[kk][1] = *reinterpret_cast<const ulonglong2*>(wb + (size_t)kk * ldw + 4);
        }
        #pragma unroll
        for (int half = 0; half < 2; half++){
            float4 xv[8];
            #pragma unroll
            for (int r = 0; r < 8; r++)
                xv[r] = *reinterpret_cast<const float4*>(X + (size_t)(r0 + half*8 + r) * HID + koff + k4);
            #pragma unroll
            for (int kk = 0; kk < 4; kk++){
                #pragma unroll
                for (int r = 0; r < 8; r++){
                    ull x2 = pack2(reinterpret_cast<const float*>(&xv[r])[kk]);
                    int ri = half*8 + r;
                    fma2(acc[ri][0], x2, w[kk][0].x);
                    fma2(acc[ri][1], x2, w[kk][0].y);
                    fma2(acc[ri][2], x2, w[kk][1].x);
                    fma2(acc[ri][3], x2, w[kk][1].y);
                }
            }
        }
    }
    #pragma unroll
    for (int ri = 0; ri < 16; ri++){
        float* pr = P + (size_t)(r0 + ri) * ldo + n0;
        ulonglong2 s0, s1;
        s0.x = acc[ri][0]; s0.y = acc[ri][1];
        s1.x = acc[ri][2]; s1.y = acc[ri][3];
        *reinterpret_cast<ulonglong2*>(pr)     = s0;
        *reinterpret_cast<ulonglong2*>(pr + 4) = s1;
    }
}

// ---------------- phases ----------------
// LSTM gemm: 256 ct * 2 rg * 2 mat * 16 slices = 16384 thread-units = 512 warp-units
__device__ __forceinline__ void phase_lstm_gemm(int l, const float* xin, const float* hin,
                                                int wu0, int lane){
    for (int v = wu0; v < 512; v += GW){
        int u  = v*32 + lane;
        int ct = u & 255;
        int rg = (u >> 8) & 1;
        int s  = u >> 9;                       // 0..31
        const float* X  = (s < 16) ? xin : hin;
        const float* WT = (s < 16) ? &g_WihT[l][0][0] : &g_WhhT[l][0][0];
        int koff = (s & 15) * 32;
        gunit16(X, rg*16, WT, 4*HID, koff, 32, &g_Pg[s][0][0], 4*HID, ct*8);
    }
}

__device__ __forceinline__ void phase_lstm_act(int l, const float* bih, const float* bhh,
                                               int wu0, int lane){
    for (int v = wu0; v < 512; v += GW){
        int b = v >> 4, j = (v & 15) * 32 + lane;
        int bo = l * 4 * HID;
        float gi = bih[bo + j]         + bhh[bo + j];
        float gf = bih[bo + HID + j]   + bhh[bo + HID + j];
        float gg = bih[bo + 2*HID + j] + bhh[bo + 2*HID + j];
        float go = bih[bo + 3*HID + j] + bhh[bo + 3*HID + j];
        #pragma unroll
        for (int s = 0; s < 32; s++){
            const float* p = &g_Pg[s][b][0];
            gi += p[j]; gf += p[HID + j]; gg += p[2*HID + j]; go += p[3*HID + j];
        }
        int idx = (l * BATCH + b) * HID + j;
        float cold = g_c[idx];
        float si = 1.f / (1.f + expf(-gi));
        float sf = 1.f / (1.f + expf(-gf));
        float so = 1.f / (1.f + expf(-go));
        float c2 = sf * cold + si * tanhf(gg);
        g_c[idx] = c2;
        float h = so * tanhf(c2);
        if (l == 0) g_h0[b][j] = h; else g_h1[b][j] = h;
        g_hcat[l*BATCH + b][j] = h;
    }
}

// proj: 1280 ct * 2 rg * 16 slices = 40960 tu = 1280 wu; q: 64 ct * 4 rg * 16 = 4096 tu = 128 wu
__device__ __forceinline__ void phase_projq(const float* X, int withQ, int wu0, int lane){
    for (int v = wu0; v < 1408; v += GW){
        if (v < 1280){
            int u  = v*32 + lane;
            int ct = u % 1280;
            int rg = (u / 1280) & 1;
            int s  = u / 2560;                 // 0..15
            gunit16(X, rg*16, &g_projWT[0][0], VP, s*32, 32,
                    &g_Pp[s][0][0], VP, ct*8);
        } else if (withQ){
            int u  = (v - 1280)*32 + lane;     // < 4096
            int ct = u & 63;
            int rg = (u >> 6) & 3;
            int s  = u >> 8;                   // 0..15
            gunit16(&g_hcat[0][0], rg*16, &g_WqT[0][0], HID, s*32, 32,
                    &g_Pq[s][0][0], HID, ct*8);
        }
    }
}

__device__ __forceinline__ void attention_warp(int aw, const float* bq, int lane){
    int lb = aw & 63, half = aw >> 6;
    int b = lb & 31;
    float qv[16];
    #pragma unroll
    for (int i = 0; i < 16; i++){
        int j = i*32 + lane;
        float a = bq[j];
        #pragma unroll
        for (int s = 0; s < 16; s++) a += g_Pq[s][lb][j];
        qv[i] = tanhf(a);
    }
    float scA = 0.f, scB = -INFINITY;
    for (int s = 0; s < SPOS; s++){
        const float* kp = &g_keys[b][s][0];
        float d = 0.f;
        #pragma unroll
        for (int i = 0; i < 16; i++) d += qv[i] * __ldg(kp + i*32 + lane);
        #pragma unroll
        for (int o = 16; o > 0; o >>= 1) d += __shfl_xor_sync(0xffffffffu, d, o);
        d *= (1.f / 7.f);
        if (lane == s)      scA = d;
        if (lane + 32 == s) scB = d;
    }
    float m = fmaxf(scA, scB);
    #pragma unroll
    for (int o = 16; o > 0; o >>= 1) m = fmaxf(m, __shfl_xor_sync(0xffffffffu, m, o));
    float eA = expf(scA - m);
    float eB = (lane + 32 < SPOS) ? expf(scB - m) : 0.f;
    float ssum = eA + eB;
    #pragma unroll
    for (int o = 16; o > 0; o >>= 1) ssum += __shfl_xor_sync(0xffffffffu, ssum, o);
    float inv = 1.f / ssum;
    float wA = eA * inv, wB = eB * inv;
    float av[8];
    #pragma unroll
    for (int i = 0; i < 8; i++) av[i] = 0.f;
    for (int s = 0; s < SPOS; s++){
        float w = (s < 32) ? __shfl_sync(0xffffffffu, wA, s)
                           : __shfl_sync(0xffffffffu, wB, s - 32);
        const float* vp = &g_vals[b][s][0];
        #pragma unroll
        for (int i = 0; i < 8; i++) av[i] += w * __ldg(vp + (half*8 + i)*32 + lane);
    }
    #pragma unroll
    for (int i = 0; i < 8; i++)
        g_attn[lb][(half*8 + i)*32 + lane] = av[i];
}

// logits: 32 b * 33 ch = 1056 wu; attn: 64 lb * 2 halves = 128 wu; total 1184 = GW
__device__ __forceinline__ void phase_logits_attn(int tslot, int withAttn,
        const float* projb, const float* bq, int wu0, int lane){
    for (int v = wu0; v < GW; v += GW){
        if (v < 1056){
            int b = v / 33, ch = v % 33;
            int vend = ch*304 + 304; if (vend > VOC) vend = VOC;
            float best = -INFINITY; int bi = 0;
            for (int vi = ch*304 + lane; vi < vend; vi += 32){
                float val = projb[vi];
                #pragma unroll
                for (int s = 0; s < 16; s++) val += g_Pp[s][b][vi];
                g_tmp[tslot][b][vi] = val;
                if (val > best){ best = val; bi = vi; }
            }
            #pragma unroll
            for (int o = 16; o > 0; o >>= 1){
                float ov = __shfl_xor_sync(0xffffffffu, best, o);
                int   oi = __shfl_xor_sync(0xffffffffu, bi, o);
                if (ov > best || (ov == best && oi < bi)){ best = ov; bi = oi; }
            }
            if (lane == 0){ g_amv[b][ch] = best; g_ami[b][ch] = bi; }
        } else if (withAttn){
            attention_warp(v - 1056, bq, lane);
        }
    }
}

// argmax 32 wu + hatt gemm: 64 ct * 4 rg * 64 slices(KC=16) = 16384 tu = 512 wu
__device__ __forceinline__ void phase_amhatt(const float* embed, int wu0, int lane){
    for (int v = wu0; v < 544; v += GW){
        if (v < 32){
            int b = v;
            float best = g_amv[b][0]; int bi = g_ami[b][0];
            for (int ch = 1; ch < 33; ch++){
                float vv = g_amv[b][ch]; int ii = g_ami[b][ch];
                if (vv > best || (vv == best && ii < bi)){ best = vv; bi = ii; }
            }
            #pragma unroll
            for (int i = 0; i < 16; i++)
                g_emb[b][i*32 + lane] = __ldg(&embed[(size_t)bi * HID + i*32 + lane]);
        } else {
            int u  = (v - 32)*32 + lane;       // < 16384
            int ct = u & 63;
            int rg = (u >> 6) & 3;
            int s  = u >> 8;                   // 0..63
            const float* X = (s < 32) ? &g_attn[0][0] : &g_hcat[0][0];
            int koff = (s & 31) * 16;
            gunit16(X, rg*16, &g_hattWT[s*16][0] - (size_t)koff*HID, HID, koff, 16,
                    &g_Ph[s][0][0], HID, ct*8);
        }
    }
}

__device__ __forceinline__ void phase_hatt_act(const float* hattb, int wu0, int lane){
    for (int v = wu0; v < 1024; v += GW){
        int lb = v >> 4, j = (v & 15) * 32 + lane;
        float a = hattb[j];
        #pragma unroll
        for (int s = 0; s < 64; s++) a += g_Ph[s][lb][j];
        float h = tanhf(a);
        int b = lb & 31;
        if (lb < 32) g_h0[b][j] = h; else g_h1[b][j] = h;
        g_hcat[lb][j] = h;
    }
}

__device__ __forceinline__ void phase_out(float* out, int wu0, int lane){
    for (int wu = wu0; wu < 10000; wu += GW){
        int e = wu*32 + lane;
        int b = e / VOC, v = e % VOC;
        float r[TMAX];
        #pragma unroll
        for (int t = 0; t < TMAX; t++) r[t] = g_tmp[t][b][v];
        float4* o4 = reinterpret_cast<float4*>(out + ((size_t)b*VOC + v)*TMAX);
        #pragma unroll
        for (int i = 0; i < 5; i++) o4[i] = reinterpret_cast<float4*>(r)[i];
    }
}

// ---------------- persistent decoder ----------------
__global__ __launch_bounds__(NT, 1)
void decoder_persistent(const float* __restrict__ bq, const float* __restrict__ bih,
                        const float* __restrict__ bhh, const float* __restrict__ projb,
                        const float* __restrict__ hattb, const float* __restrict__ embed,
                        float* __restrict__ out){
    int wu0 = (threadIdx.x >> 5) * NB + blockIdx.x;
    int lane = threadIdx.x & 31;

    phase_projq(&g_emb[0][0], 0, wu0, lane);
    gridbar();
    phase_logits_attn(0, 0, projb, bq, wu0, lane);
    gridbar();

    for (int t = 0; t < TMAX - 1; t++){
        phase_lstm_gemm(0, &g_emb[0][0], &g_h0[0][0], wu0, lane);
        gridbar();
        phase_lstm_act(0, bih, bhh, wu0, lane);
        gridbar();
        phase_lstm_gemm(1, &g_h0[0][0], &g_h1[0][0], wu0, lane);
        gridbar();
        phase_lstm_act(1, bih, bhh, wu0, lane);
        gridbar();
        int more = (t < TMAX - 2);
        phase_projq(&g_h1[0][0], more, wu0, lane);
        gridbar();
        phase_logits_attn(t + 1, more, projb, bq, wu0, lane);
        gridbar();
        if (more){
            phase_amhatt(embed, wu0, lane);
            gridbar();
            phase_hatt_act(hattb, wu0, lane);
            gridbar();
        }
    }
    phase_out(out, wu0, lane);
}

// ---------------- setup kernels ----------------
__global__ void transpose_pad(const float* __restrict__ W, float* __restrict__ WT,
                              int N, int K, int Npad){
    __shared__ float t[32][33];
    int n0 = blockIdx.x * 32, k0 = blockIdx.y * 32;
    int tx = threadIdx.x, ty = threadIdx.y;
    int n = n0 + ty, k = k0 + tx;
    float v = 0.f;
    if (n < N && k < K) v = W[(size_t)n * K + k];
    t[ty][tx] = v;
    __syncthreads();
    int kk = k0 + ty, nn = n0 + tx;
    if (kk < K && nn < Npad) WT[(size_t)kk * Npad + nn] = t[tx][ty];
}

__global__ void precompute_kv(const float* __restrict__ img, const float* __restrict__ Wk,
                              const float* __restrict__ bk, const float* __restrict__ Wv,
                              const float* __restrict__ bv){
    __shared__ float wk_s[SPOS][SPOS], wv_s[SPOS][SPOS];
    __shared__ float bk_s[SPOS], bv_s[SPOS];
    int tid = threadIdx.x;
    for (int i = tid; i < SPOS*SPOS; i += 128){ wk_s[i/SPOS][i%SPOS] = Wk[i]; wv_s[i/SPOS][i%SPOS] = Wv[i]; }
    if (tid < SPOS){ bk_s[tid] = bk[tid]; bv_s[tid] = bv[tid]; }
    __syncthreads();
    int b = blockIdx.x;
    int d = blockIdx.y * 128 + tid;
    float ch[SPOS];
    const float* cp = img + ((size_t)b * HID + d) * SPOS;
    #pragma unroll
    for (int s = 0; s < SPOS; s++) ch[s] = cp[s];
    for (int s = 0; s < SPOS; s++){
        float ak = bk_s[s], av = bv_s[s];
        #pragma unroll
        for (int sp = 0; sp < SPOS; sp++){ ak += ch[sp] * wk_s[s][sp]; av += ch[sp] * wv_s[s][sp]; }
        g_keys[b][s][d] = tanhf(ak);
        g_vals[b][s][d] = tanhf(av);
    }
}

__global__ void init_state(const float* __restrict__ pooled, const float* __restrict__ embed,
                           const int* __restrict__ sos){
    int idx = blockIdx.x * blockDim.x + threadIdx.x;
    if (idx >= BATCH * HID) return;
    int b = idx >> 9, j = idx & 511;
    float p = pooled[b * HID + j];
    g_c[(0*BATCH + b)*HID + j] = p;
    g_c[(1*BATCH + b)*HID + j] = p;
    g_h0[b][j] = p;
    g_h1[b][j] = p;
    g_hcat[b][j] = p;
    g_hcat[BATCH + b][j] = p;
    g_emb[b][j] = embed[(size_t)(*sos) * HID + j];
}

// ---------------- host ----------------
static void* symaddr(const void* sym){
    void* p = nullptr;
    cudaGetSymbolAddress(&p, sym);
    return p;
}

extern "C" void kernel_launch(void* const* d_in, const int* in_sizes, int n_in,
                              void* d_out, int out_size){
    const float* img    = (const float*)d_in[0];
    const float* pooled = (const float*)d_in[1];
    const float* embed  = (const float*)d_in[2];
    const float* Wq     = (const float*)d_in[3];
    const float* bq     = (const float*)d_in[4];
    const float* Wk     = (const float*)d_in[5];
    const float* bk     = (const float*)d_in[6];
    const float* Wv     = (const float*)d_in[7];
    const float* bv     = (const float*)d_in[8];
    const float* Wih    = (const float*)d_in[9];
    const float* Whh    = (const float*)d_in[10];
    const float* bih    = (const float*)d_in[11];
    const float* bhh    = (const float*)d_in[12];
    const float* projW  = (const float*)d_in[13];
    const float* projb  = (const float*)d_in[14];
    const float* hattW  = (const float*)d_in[15];
    const float* hattb  = (const float*)d_in[16];
    const int*   sos    = (const int*)d_in[17];

    float* WihT   = (float*)symaddr(g_WihT);
    float* WhhT   = (float*)symaddr(g_WhhT);
    float* WqT    = (float*)symaddr(g_WqT);
    float* hattWT = (float*)symaddr(g_hattWT);
    float* projWT = (float*)symaddr(g_projWT);

    dim3 tb(32, 32);
    transpose_pad<<<dim3(16, 16),  tb>>>(Wq,    WqT,    HID,  HID,   HID);
    transpose_pad<<<dim3(16, 32),  tb>>>(hattW, hattWT, HID,  2*HID, HID);
    transpose_pad<<<dim3(320, 16), tb>>>(projW, projWT, VOC,  HID,   VP);   // 320*32 = 10240 = VP
    for (int l = 0; l < L2L; l++){
        transpose_pad<<<dim3(64, 16), tb>>>(Wih + (size_t)l*4*HID*HID, WihT + (size_t)l*HID*4*HID, 4*HID, HID, 4*HID);
        transpose_pad<<<dim3(64, 16), tb>>>(Whh + (size_t)l*4*HID*HID, WhhT + (size_t)l*HID*4*HID, 4*HID, HID, 4*HID);
    }
    precompute_kv<<<dim3(BATCH, 4), 128>>>(img, Wk, bk, Wv, bv);
    init_state<<<64, 256>>>(pooled, embed, sos);

    decoder_persistent<<<NB, NT>>>(bq, bih, bhh, projb, hattb, embed, (float*)d_out);
}